// round 15
// baseline (speedup 1.0000x reference)
#include <cuda_runtime.h>
#include <cuda_fp16.h>
#include <stdint.h>

// ---------------- problem sizes ----------------
#define BB 2
#define NN 4096
#define EE 512
#define HH 8
#define DD 64
#define MMR (BB*NN)            // 8192
#define E1  (MMR*EE)           // 4194304

// Q prescale: log2(e)/8, folded into the Q projection epilogue
#define QSCALE 0.18033688011112042f

// ---------------- scratch ----------------
__device__ __align__(256) __half g_scratch[6u*E1];

#define SWZ(o) ((o) ^ (((o) >> 3) & 0x70))

__device__ __forceinline__ uint32_t smem_u32(const void* p) {
    uint32_t a;
    asm("{ .reg .u64 t; cvta.to.shared.u64 t, %1; cvt.u32.u64 %0, t; }" : "=r"(a) : "l"(p));
    return a;
}
__device__ __forceinline__ void mma_f16(float c[4], const uint32_t a[4], const uint32_t b[2]) {
    asm volatile("mma.sync.aligned.m16n8k16.row.col.f32.f16.f16.f32 "
        "{%0,%1,%2,%3}, {%4,%5,%6,%7}, {%8,%9}, {%0,%1,%2,%3};"
        : "+f"(c[0]), "+f"(c[1]), "+f"(c[2]), "+f"(c[3])
        : "r"(a[0]), "r"(a[1]), "r"(a[2]), "r"(a[3]), "r"(b[0]), "r"(b[1]));
}
// fp16-accumulator variant: D = {d0,d1} packed f16x2; layout == PV A-fragment
__device__ __forceinline__ void mma_f16h(uint32_t d[2], const uint32_t a[4], const uint32_t b[2]) {
    asm volatile("mma.sync.aligned.m16n8k16.row.col.f16.f16.f16.f16 "
        "{%0,%1}, {%2,%3,%4,%5}, {%6,%7}, {%0,%1};"
        : "+r"(d[0]), "+r"(d[1])
        : "r"(a[0]), "r"(a[1]), "r"(a[2]), "r"(a[3]), "r"(b[0]), "r"(b[1]));
}
__device__ __forceinline__ void ldsm4(uint32_t r[4], uint32_t addr) {
    asm volatile("ldmatrix.sync.aligned.m8n8.x4.shared.b16 {%0,%1,%2,%3}, [%4];"
        : "=r"(r[0]), "=r"(r[1]), "=r"(r[2]), "=r"(r[3]) : "r"(addr));
}
__device__ __forceinline__ uint32_t h2ex2(uint32_t x) {
    uint32_t r;
    asm("ex2.approx.f16x2 %0, %1;" : "=r"(r) : "r"(x));
    return r;
}
__device__ __forceinline__ uint32_t hadd2(uint32_t a, uint32_t b) {
    uint32_t r;
    asm("add.f16x2 %0, %1, %2;" : "=r"(r) : "r"(a), "r"(b));
    return r;
}
__device__ __forceinline__ float2 h2f2(uint32_t p) {
    __half2 h = *reinterpret_cast<__half2*>(&p);
    return __half22float2(h);
}
// A-operand x4: 16x16 tile at (rowbase, colByte); rows of 128B, SW128 swizzled
__device__ __forceinline__ uint32_t addrA(uint32_t base, int rowbase, int colByte, int lane) {
    int row = rowbase + (lane & 7) + (lane & 8);
    int col = colByte + ((lane >> 4) << 4);
    uint32_t off = (uint32_t)(row * 128 + col);
    return base + SWZ(off);
}
// B-operand x4: two n-tiles (16 rows) x 16 k-bytes
__device__ __forceinline__ uint32_t addrB(uint32_t base, int nbase, int kByte, int lane) {
    int row = nbase + (lane & 7) + (((lane >> 4) & 1) << 3);
    int col = kByte + (((lane >> 3) & 1) << 4);
    uint32_t off = (uint32_t)(row * 128 + col);
    return base + SWZ(off);
}
__device__ __forceinline__ uint32_t pack_f16(float lo, float hi) {
    uint32_t r;
    asm("cvt.rn.f16x2.f32 %0, %1, %2;" : "=r"(r) : "f"(hi), "f"(lo));
    return r;
}

// ---------------- tile loaders: nrows x 64 cols, SW128 rows of 128B ----------------
template<int NT>
__device__ __forceinline__ void load_tile(const __half* __restrict__ g,
                                          size_t row0, int stride, int k0,
                                          char* sdst, int nrows, int tid)
{
    const int total = nrows * 16;
    for (int i = tid; i < total; i += NT) {
        int r = i >> 4, c = i & 15;
        uint2 v = *reinterpret_cast<const uint2*>(g + (row0 + r) * (size_t)stride + k0 + c * 4);
        *reinterpret_cast<uint2*>(sdst + SWZ((uint32_t)(r * 128 + c * 8))) = v;
    }
}
template<int NT>
__device__ __forceinline__ void load_tile_f32(const float* __restrict__ g,
                                              size_t row0, int stride, int k0,
                                              char* sdst, int nrows, int tid)
{
    const int total = nrows * 16;
    for (int i = tid; i < total; i += NT) {
        int r = i >> 4, c = i & 15;
        float4 f = *reinterpret_cast<const float4*>(g + (row0 + r) * (size_t)stride + k0 + c * 4);
        uint2 v = make_uint2(pack_f16(f.x, f.y), pack_f16(f.z, f.w));
        *reinterpret_cast<uint2*>(sdst + SWZ((uint32_t)(r * 128 + c * 8))) = v;
    }
}

// ---- register prefetch, fp16: 64 rows x 64 cols, 128 threads (attention) ----
__device__ __forceinline__ void pf_ld64s(const __half* __restrict__ g,
                                         size_t row0, int stride, int k0,
                                         uint4 r[4], int tid)
{
#pragma unroll
    for (int i = 0; i < 4; i++) {
        int idx = tid + i * 128;
        int rr = idx >> 3, cc = idx & 7;
        r[i] = *reinterpret_cast<const uint4*>(g + (row0 + rr) * (size_t)stride + k0 + cc * 8);
    }
}
__device__ __forceinline__ void pf_st64s(const uint4 r[4], char* s, int tid)
{
#pragma unroll
    for (int i = 0; i < 4; i++) {
        int idx = tid + i * 128;
        int rr = idx >> 3, cc = idx & 7;
        *reinterpret_cast<uint4*>(s + SWZ((uint32_t)(rr * 128 + cc * 16))) = r[i];
    }
}

// ---- GEMM register prefetch (256 threads), convert-at-load fp32 -> fp16x2 (16 regs) ----
__device__ __forceinline__ void pf_ld128fc(const float* __restrict__ g,
                                           size_t row0, int stride, int k0,
                                           uint2 r[8], int tid)
{
#pragma unroll
    for (int i = 0; i < 8; i++) {
        int idx = tid + i * 256;        // 0..2047
        int rr = idx >> 4, cc = idx & 15;
        float4 f = *reinterpret_cast<const float4*>(g + (row0 + rr) * (size_t)stride + k0 + cc * 4);
        r[i] = make_uint2(pack_f16(f.x, f.y), pack_f16(f.z, f.w));
    }
}
__device__ __forceinline__ void pf_st128c(const uint2 r[8], char* s, int tid)
{
#pragma unroll
    for (int i = 0; i < 8; i++) {
        int idx = tid + i * 256;
        int rr = idx >> 4, cc = idx & 15;
        *reinterpret_cast<uint2*>(s + SWZ((uint32_t)(rr * 128 + cc * 8))) = r[i];
    }
}
// ---- GEMM register prefetch (256 threads), fp16 source (16 regs) ----
__device__ __forceinline__ void pf_ld128h(const __half* __restrict__ g,
                                          size_t row0, int stride, int k0, uint4 r[4], int tid)
{
#pragma unroll
    for (int i = 0; i < 4; i++) {
        int idx = tid + i * 256;
        int rr = idx >> 3, cc = idx & 7;
        r[i] = *reinterpret_cast<const uint4*>(g + (row0 + rr) * (size_t)stride + k0 + cc * 8);
    }
}
__device__ __forceinline__ void pf_st128h(const uint4 r[4], char* s, int tid)
{
#pragma unroll
    for (int i = 0; i < 4; i++) {
        int idx = tid + i * 256;
        int rr = idx >> 3, cc = idx & 7;
        *reinterpret_cast<uint4*>(s + SWZ((uint32_t)(rr * 128 + cc * 16))) = r[i];
    }
}

// ---------------- fused QKV projection, 128x128 tiles, double-buffered, 1 sync/chunk ----------------
// smem: A0@0, B0@16K, A1@32K, B1@48K  (64KB/CTA, 2 CTAs/SM)
#define G_SMEM 65536

__global__ void __launch_bounds__(256, 2) gemm_qkv(
    const float* __restrict__ q, const float* __restrict__ k, const float* __restrict__ v,
    const float* __restrict__ Wq, const float* __restrict__ Wk, const float* __restrict__ Wv,
    const float* __restrict__ bq, const float* __restrict__ bk, const float* __restrict__ bv,
    __half* __restrict__ qp, __half* __restrict__ kp, __half* __restrict__ vtp)
{
    extern __shared__ char sm[];
    const int z = blockIdx.z;
    const float* X    = (z == 0) ? q  : (z == 1) ? k  : v;
    const float* W    = (z == 0) ? Wq : (z == 1) ? Wk : Wv;
    const float* bias = (z == 0) ? bq : (z == 1) ? bk : bv;
    __half* Oh        = (z == 0) ? qp : (z == 1) ? kp : vtp;
    const float oscale = (z == 0) ? QSCALE : 1.0f;

    const int tid = threadIdx.x, lane = tid & 31, wid = tid >> 5;
    const int wm = wid & 3, wn = wid >> 2;
    const int m0 = blockIdx.y * 128, n0 = blockIdx.x * 128;
    const uint32_t sb = smem_u32(sm);

    load_tile_f32<256>(X, (size_t)m0, EE, 0, sm + 0,     128, tid);
    load_tile_f32<256>(W, (size_t)n0, EE, 0, sm + 16384, 128, tid);
    __syncthreads();

    float c[2][8][4] = {};

    for (int chunk = 0; chunk < 8; chunk++) {
        const uint32_t cur = (chunk & 1) * 32768;
        uint2 pa[8], pb[8];
        if (chunk < 7) {
            const int k0 = (chunk + 1) * 64;
            pf_ld128fc(X, (size_t)m0, EE, k0, pa, tid);
            pf_ld128fc(W, (size_t)n0, EE, k0, pb, tid);
        }
#pragma unroll
        for (int kk = 0; kk < 4; kk++) {
            uint32_t af[2][4];
            ldsm4(af[0], addrA(sb + cur + 0, 32*wm,      kk*32, lane));
            ldsm4(af[1], addrA(sb + cur + 0, 32*wm + 16, kk*32, lane));
#pragma unroll
            for (int t = 0; t < 4; t++) {
                uint32_t bh[4];
                ldsm4(bh, addrB(sb + cur + 16384, 64*wn + 16*t, kk*32, lane));
#pragma unroll
                for (int mt = 0; mt < 2; mt++) {
                    mma_f16(c[mt][2*t],   af[mt], bh);
                    mma_f16(c[mt][2*t+1], af[mt], bh + 2);
                }
            }
        }
        if (chunk < 7) {
            const uint32_t oth = ((chunk + 1) & 1) * 32768;
            pf_st128c(pa, sm + oth + 0,     tid);
            pf_st128c(pb, sm + oth + 16384, tid);
        }
        __syncthreads();
    }

    const int g = lane >> 2, tig = lane & 3;
    if (z != 2) {
        // Q/K: [B,H,N,D], half2 stores
#pragma unroll
        for (int mt = 0; mt < 2; mt++) {
#pragma unroll
            for (int t = 0; t < 8; t++) {
                const int e = n0 + 64*wn + 8*t + 2*tig;
                const float bv0 = bias[e], bv1 = bias[e + 1];
#pragma unroll
                for (int hf = 0; hf < 2; hf++) {
                    const int m = m0 + 32*wm + 16*mt + g + 8*hf;
                    const float v0 = (c[mt][t][2*hf] + bv0) * oscale;
                    const float v1 = (c[mt][t][2*hf + 1] + bv1) * oscale;
                    const int bb = m >> 12, nn = m & (NN - 1);
                    const int hh = e >> 6, d = e & 63;
                    size_t idx = (((size_t)bb*HH + hh)*NN + nn)*DD + d;
                    *reinterpret_cast<uint32_t*>(Oh + idx) = pack_f16(v0, v1);
                }
            }
        }
    } else {
        // V: stage through smem (free after mainloop), emit coalesced [B,H,D,N] rows
        __half* st = reinterpret_cast<__half*>(sm);     // [128 e][136 pad] halves = 34.8KB
#pragma unroll
        for (int mt = 0; mt < 2; mt++) {
#pragma unroll
            for (int t = 0; t < 8; t++) {
                const int el = 64*wn + 8*t + 2*tig;
                const float bv0 = bias[n0 + el], bv1 = bias[n0 + el + 1];
#pragma unroll
                for (int hf = 0; hf < 2; hf++) {
                    const int ml = 32*wm + 16*mt + g + 8*hf;
                    st[el * 136 + ml]       = __float2half_rn(c[mt][t][2*hf] + bv0);
                    st[(el + 1) * 136 + ml] = __float2half_rn(c[mt][t][2*hf + 1] + bv1);
                }
            }
        }
        __syncthreads();
        const int bb = m0 >> 12;
        const int nbase = m0 & (NN - 1);
#pragma unroll
        for (int j = 0; j < 8; j++) {
            int i = tid + j * 256;          // 0..2047
            int r = i >> 4, cc = i & 15;    // e row, 8-half chunk
            uint4 val = *reinterpret_cast<const uint4*>(st + r * 136 + cc * 8);
            const int eg = n0 + r;
            const int hh = eg >> 6, d = eg & 63;
            *reinterpret_cast<uint4*>(Oh + (((size_t)bb*HH + hh)*DD + d)*NN + nbase + cc*8) = val;
        }
    }
}

// ---------------- output projection, 128x128 tiles, double-buffered, 1 sync/chunk ----------------
__global__ void __launch_bounds__(256, 2) gemm_o(
    const __half* __restrict__ A16, const float* __restrict__ W,
    const float* __restrict__ bias, float* __restrict__ Of)
{
    extern __shared__ char sm[];
    const int tid = threadIdx.x, lane = tid & 31, wid = tid >> 5;
    const int wm = wid & 3, wn = wid >> 2;
    const int m0 = blockIdx.y * 128, n0 = blockIdx.x * 128;
    const uint32_t sb = smem_u32(sm);

    load_tile<256>(A16, (size_t)m0, EE, 0, sm + 0,     128, tid);
    load_tile_f32<256>(W, (size_t)n0, EE, 0, sm + 16384, 128, tid);
    __syncthreads();

    float c[2][8][4] = {};

    for (int chunk = 0; chunk < 8; chunk++) {
        const uint32_t cur = (chunk & 1) * 32768;
        uint4 pa[4]; uint2 pb[8];
        if (chunk < 7) {
            const int k0 = (chunk + 1) * 64;
            pf_ld128h(A16, (size_t)m0, EE, k0, pa, tid);
            pf_ld128fc(W, (size_t)n0, EE, k0, pb, tid);
        }
#pragma unroll
        for (int kk = 0; kk < 4; kk++) {
            uint32_t af[2][4];
            ldsm4(af[0], addrA(sb + cur + 0, 32*wm,      kk*32, lane));
            ldsm4(af[1], addrA(sb + cur + 0, 32*wm + 16, kk*32, lane));
#pragma unroll
            for (int t = 0; t < 4; t++) {
                uint32_t bh[4];
                ldsm4(bh, addrB(sb + cur + 16384, 64*wn + 16*t, kk*32, lane));
#pragma unroll
                for (int mt = 0; mt < 2; mt++) {
                    mma_f16(c[mt][2*t],   af[mt], bh);
                    mma_f16(c[mt][2*t+1], af[mt], bh + 2);
                }
            }
        }
        if (chunk < 7) {
            const uint32_t oth = ((chunk + 1) & 1) * 32768;
            pf_st128h(pa, sm + oth + 0,     tid);
            pf_st128c(pb, sm + oth + 16384, tid);
        }
        __syncthreads();
    }

    const int g = lane >> 2, tig = lane & 3;
#pragma unroll
    for (int mt = 0; mt < 2; mt++) {
#pragma unroll
        for (int t = 0; t < 8; t++) {
            const int e = n0 + 64*wn + 8*t + 2*tig;
            const float bv0 = bias[e], bv1 = bias[e + 1];
#pragma unroll
            for (int hf = 0; hf < 2; hf++) {
                const int m = m0 + 32*wm + 16*mt + g + 8*hf;
                *reinterpret_cast<float2*>(Of + (size_t)m * EE + e) =
                    make_float2(c[mt][t][2*hf] + bv0, c[mt][t][2*hf + 1] + bv1);
            }
        }
    }
}

// ---------------- flash attention: fp16-accum S (zero packs), 128-key super-tiles ----------------
// CTA = 128 q-rows of one (b,h); 4 warps x 32 q-rows; 32 super-tiles of 128 keys;
// 1 sync per super-tile. smem: Q 16KB + 2 stages x 32KB (K0,V0,K1,V1 of 8KB) = 80KB; 2 CTAs/SM.
#define A_QH 0
#define A_KV0 16384
#define A_STG 32768
#define A_SMEM 81920

__global__ void __launch_bounds__(128, 2) attn_mma(
    const __half* __restrict__ qp, const __half* __restrict__ kp,
    const __half* __restrict__ vt, __half* __restrict__ att)
{
    extern __shared__ char sm[];
    const int tid = threadIdx.x, lane = tid & 31, wid = tid >> 5;
    const int b = blockIdx.z, h = blockIdx.y, i0 = blockIdx.x * 128;
    const int bh = b * HH + h;
    const uint32_t sb = smem_u32(sm);

    load_tile<128>(qp, (size_t)bh * NN + i0, DD, 0, sm + A_QH, 128, tid);
    // super-tile 0: K0/V0 (keys 0..63) and K1/V1 (keys 64..127)
    load_tile<128>(kp, (size_t)bh * NN,      DD, 0,  sm + A_KV0 + 0,     64, tid);
    load_tile<128>(vt, (size_t)bh * DD, NN,  0,      sm + A_KV0 + 8192,  64, tid);
    load_tile<128>(kp, (size_t)bh * NN + 64, DD, 0,  sm + A_KV0 + 16384, 64, tid);
    load_tile<128>(vt, (size_t)bh * DD, NN,  64,     sm + A_KV0 + 24576, 64, tid);
    __syncthreads();

    // Q fragments hoisted: constant across all key tiles
    uint32_t qf[4][2][4];
#pragma unroll
    for (int kk = 0; kk < 4; kk++) {
        ldsm4(qf[kk][0], addrA(sb + A_QH, 32*wid,      kk*32, lane));
        ldsm4(qf[kk][1], addrA(sb + A_QH, 32*wid + 16, kk*32, lane));
    }

    float o[2][8][4] = {};
    float lsum[2][2] = {};

    for (int st = 0; st < 32; st++) {
        const uint32_t cur = sb + A_KV0 + (st & 1) * A_STG;
        char* nxt = sm + A_KV0 + ((st + 1) & 1) * A_STG;

#pragma unroll
        for (int half = 0; half < 2; half++) {
            const uint32_t bK = cur + half * 16384;
            const uint32_t bV = bK + 8192;
            const int nkey = (2 * st + 2 + half) * 64;     // next super-tile, same half

            uint4 kreg[4], vreg[4];
            if (st < 31) {
                pf_ld64s(kp, (size_t)bh * NN + nkey, DD, 0, kreg, tid);
                pf_ld64s(vt, (size_t)bh * DD, NN, nkey, vreg, tid);
            }

            // fp16 S accumulators: hsc[mt][nt][2] — D layout == PV A-fragment
            uint32_t hsc[2][8][2] = {};

            // exp + PV for key-slice j (16 keys): ex2 directly on fp16 accumulators
            auto exp_pv = [&](int j) {
                uint32_t ah[2][4];
#pragma unroll
                for (int mt = 0; mt < 2; mt++) {
                    ah[mt][0] = h2ex2(hsc[mt][2*j][0]);      // row g,   keys 2tig..
                    ah[mt][1] = h2ex2(hsc[mt][2*j][1]);      // row g+8, keys 2tig..
                    ah[mt][2] = h2ex2(hsc[mt][2*j+1][0]);    // row g,   keys 8+2tig..
                    ah[mt][3] = h2ex2(hsc[mt][2*j+1][1]);    // row g+8, keys 8+2tig..
                    float2 f01 = h2f2(hadd2(ah[mt][0], ah[mt][2]));   // row g
                    float2 f23 = h2f2(hadd2(ah[mt][1], ah[mt][3]));   // row g+8
                    lsum[mt][0] += f01.x + f01.y;
                    lsum[mt][1] += f23.x + f23.y;
                }
#pragma unroll
                for (int tv = 0; tv < 4; tv++) {
                    uint32_t vh[4];
                    ldsm4(vh, addrB(bV, 16*tv, j*32, lane));
#pragma unroll
                    for (int mt = 0; mt < 2; mt++) {
                        mma_f16(o[mt][2*tv],   ah[mt], vh);
                        mma_f16(o[mt][2*tv+1], ah[mt], vh + 2);
                    }
                }
            };

#pragma unroll
            for (int tt = 0; tt < 4; tt++) {
#pragma unroll
                for (int kk = 0; kk < 4; kk++) {
                    uint32_t bhf[4];
                    ldsm4(bhf, addrB(bK, 16*tt, kk*32, lane));
#pragma unroll
                    for (int mt = 0; mt < 2; mt++) {
                        mma_f16h(hsc[mt][2*tt],   qf[kk][mt], bhf);
                        mma_f16h(hsc[mt][2*tt+1], qf[kk][mt], bhf + 2);
                    }
                }
                if (tt > 0) exp_pv(tt - 1);
            }
            exp_pv(3);

            if (st < 31) {
                pf_st64s(kreg, nxt + half * 16384, tid);
                pf_st64s(vreg, nxt + half * 16384 + 8192, tid);
            }
        }
        __syncthreads();
    }

    // ---- reduce row sums across the 4 tig lanes, normalize, write fp16 ----
#pragma unroll
    for (int mt = 0; mt < 2; mt++)
#pragma unroll
        for (int hf = 0; hf < 2; hf++) {
            float s = lsum[mt][hf];
            s += __shfl_xor_sync(0xffffffffu, s, 1);
            s += __shfl_xor_sync(0xffffffffu, s, 2);
            lsum[mt][hf] = 1.0f / s;
        }

    const int g = lane >> 2, tig = lane & 3;
#pragma unroll
    for (int mt = 0; mt < 2; mt++) {
#pragma unroll
        for (int nt = 0; nt < 8; nt++) {
            const int d = 8*nt + 2*tig;
#pragma unroll
            for (int hf = 0; hf < 2; hf++) {
                const float inv = lsum[mt][hf];
                const int row = i0 + 32*wid + 16*mt + g + 8*hf;
                const size_t idx = ((size_t)b * NN + row) * EE + h * DD + d;
                *reinterpret_cast<uint32_t*>(att + idx) =
                    pack_f16(o[mt][nt][2*hf] * inv, o[mt][nt][2*hf + 1] * inv);
            }
        }
    }
}

// ---------------- host ----------------
extern "C" void kernel_launch(void* const* d_in, const int* in_sizes, int n_in,
                              void* d_out, int out_size)
{
    const float* q  = (const float*)d_in[0];
    const float* k  = (const float*)d_in[1];
    const float* v  = (const float*)d_in[2];
    const float* Wq = (const float*)d_in[3];
    const float* bq = (const float*)d_in[4];
    const float* Wk = (const float*)d_in[5];
    const float* bk = (const float*)d_in[6];
    const float* Wv = (const float*)d_in[7];
    const float* bv = (const float*)d_in[8];
    const float* Wo = (const float*)d_in[9];
    const float* bo = (const float*)d_in[10];
    float* out = (float*)d_out;

    __half* s;
    cudaGetSymbolAddress((void**)&s, g_scratch);
    __half *qp  = s,
           *kp  = s + (size_t)E1,
           *vtp = s + 2*(size_t)E1,
           *att = s + 3*(size_t)E1;

    cudaFuncSetAttribute(gemm_qkv, cudaFuncAttributeMaxDynamicSharedMemorySize, G_SMEM);
    cudaFuncSetAttribute(gemm_o,   cudaFuncAttributeMaxDynamicSharedMemorySize, G_SMEM);
    cudaFuncSetAttribute(attn_mma, cudaFuncAttributeMaxDynamicSharedMemorySize, A_SMEM);

    gemm_qkv<<<dim3(EE/128, MMR/128, 3), 256, G_SMEM>>>(
        q, k, v, Wq, Wk, Wv, bq, bk, bv, qp, kp, vtp);

    attn_mma<<<dim3(NN/128, HH, BB), 128, A_SMEM>>>(qp, kp, vtp, att);

    gemm_o<<<dim3(EE/128, MMR/128), 256, G_SMEM>>>(att, Wo, bo, out);
}

// round 16
// speedup vs baseline: 1.0309x; 1.0309x over previous
#include <cuda_runtime.h>
#include <cuda_fp16.h>
#include <stdint.h>

// ---------------- problem sizes ----------------
#define BB 2
#define NN 4096
#define EE 512
#define HH 8
#define DD 64
#define MMR (BB*NN)            // 8192
#define E1  (MMR*EE)           // 4194304

// Q prescale: log2(e)/8, folded into the Q projection epilogue
#define QSCALE 0.18033688011112042f

// ---------------- scratch ----------------
__device__ __align__(256) __half g_scratch[6u*E1];

#define SWZ(o) ((o) ^ (((o) >> 3) & 0x70))

__device__ __forceinline__ uint32_t smem_u32(const void* p) {
    uint32_t a;
    asm("{ .reg .u64 t; cvta.to.shared.u64 t, %1; cvt.u32.u64 %0, t; }" : "=r"(a) : "l"(p));
    return a;
}
__device__ __forceinline__ void mma_f16(float c[4], const uint32_t a[4], const uint32_t b[2]) {
    asm volatile("mma.sync.aligned.m16n8k16.row.col.f32.f16.f16.f32 "
        "{%0,%1,%2,%3}, {%4,%5,%6,%7}, {%8,%9}, {%0,%1,%2,%3};"
        : "+f"(c[0]), "+f"(c[1]), "+f"(c[2]), "+f"(c[3])
        : "r"(a[0]), "r"(a[1]), "r"(a[2]), "r"(a[3]), "r"(b[0]), "r"(b[1]));
}
// fp16-accumulator variant: D = {d0,d1} packed f16x2; layout == PV A-fragment
__device__ __forceinline__ void mma_f16h(uint32_t d[2], const uint32_t a[4], const uint32_t b[2]) {
    asm volatile("mma.sync.aligned.m16n8k16.row.col.f16.f16.f16.f16 "
        "{%0,%1}, {%2,%3,%4,%5}, {%6,%7}, {%0,%1};"
        : "+r"(d[0]), "+r"(d[1])
        : "r"(a[0]), "r"(a[1]), "r"(a[2]), "r"(a[3]), "r"(b[0]), "r"(b[1]));
}
__device__ __forceinline__ void ldsm4(uint32_t r[4], uint32_t addr) {
    asm volatile("ldmatrix.sync.aligned.m8n8.x4.shared.b16 {%0,%1,%2,%3}, [%4];"
        : "=r"(r[0]), "=r"(r[1]), "=r"(r[2]), "=r"(r[3]) : "r"(addr));
}
__device__ __forceinline__ uint32_t h2ex2(uint32_t x) {
    uint32_t r;
    asm("ex2.approx.f16x2 %0, %1;" : "=r"(r) : "r"(x));
    return r;
}
__device__ __forceinline__ uint32_t hadd2(uint32_t a, uint32_t b) {
    uint32_t r;
    asm("add.f16x2 %0, %1, %2;" : "=r"(r) : "r"(a), "r"(b));
    return r;
}
__device__ __forceinline__ float2 h2f2(uint32_t p) {
    __half2 h = *reinterpret_cast<__half2*>(&p);
    return __half22float2(h);
}
// A-operand x4: 16x16 tile at (rowbase, colByte); rows of 128B, SW128 swizzled
__device__ __forceinline__ uint32_t addrA(uint32_t base, int rowbase, int colByte, int lane) {
    int row = rowbase + (lane & 7) + (lane & 8);
    int col = colByte + ((lane >> 4) << 4);
    uint32_t off = (uint32_t)(row * 128 + col);
    return base + SWZ(off);
}
// B-operand x4: two n-tiles (16 rows) x 16 k-bytes
__device__ __forceinline__ uint32_t addrB(uint32_t base, int nbase, int kByte, int lane) {
    int row = nbase + (lane & 7) + (((lane >> 4) & 1) << 3);
    int col = kByte + (((lane >> 3) & 1) << 4);
    uint32_t off = (uint32_t)(row * 128 + col);
    return base + SWZ(off);
}
__device__ __forceinline__ uint32_t pack_f16(float lo, float hi) {
    uint32_t r;
    asm("cvt.rn.f16x2.f32 %0, %1, %2;" : "=r"(r) : "f"(hi), "f"(lo));
    return r;
}

// ---------------- tile loaders: nrows x 64 cols, SW128 rows of 128B ----------------
template<int NT>
__device__ __forceinline__ void load_tile(const __half* __restrict__ g,
                                          size_t row0, int stride, int k0,
                                          char* sdst, int nrows, int tid)
{
    const int total = nrows * 16;
    for (int i = tid; i < total; i += NT) {
        int r = i >> 4, c = i & 15;
        uint2 v = *reinterpret_cast<const uint2*>(g + (row0 + r) * (size_t)stride + k0 + c * 4);
        *reinterpret_cast<uint2*>(sdst + SWZ((uint32_t)(r * 128 + c * 8))) = v;
    }
}
template<int NT>
__device__ __forceinline__ void load_tile_f32(const float* __restrict__ g,
                                              size_t row0, int stride, int k0,
                                              char* sdst, int nrows, int tid)
{
    const int total = nrows * 16;
    for (int i = tid; i < total; i += NT) {
        int r = i >> 4, c = i & 15;
        float4 f = *reinterpret_cast<const float4*>(g + (row0 + r) * (size_t)stride + k0 + c * 4);
        uint2 v = make_uint2(pack_f16(f.x, f.y), pack_f16(f.z, f.w));
        *reinterpret_cast<uint2*>(sdst + SWZ((uint32_t)(r * 128 + c * 8))) = v;
    }
}

// ---- register prefetch, fp16: 64 rows x 64 cols, 128 threads (attention) ----
__device__ __forceinline__ void pf_ld64s(const __half* __restrict__ g,
                                         size_t row0, int stride, int k0,
                                         uint4 r[4], int tid)
{
#pragma unroll
    for (int i = 0; i < 4; i++) {
        int idx = tid + i * 128;
        int rr = idx >> 3, cc = idx & 7;
        r[i] = *reinterpret_cast<const uint4*>(g + (row0 + rr) * (size_t)stride + k0 + cc * 8);
    }
}
__device__ __forceinline__ void pf_st64s(const uint4 r[4], char* s, int tid)
{
#pragma unroll
    for (int i = 0; i < 4; i++) {
        int idx = tid + i * 128;
        int rr = idx >> 3, cc = idx & 7;
        *reinterpret_cast<uint4*>(s + SWZ((uint32_t)(rr * 128 + cc * 16))) = r[i];
    }
}

// ---- GEMM register prefetch (256 threads), convert-at-load fp32 -> fp16x2 (16 regs) ----
__device__ __forceinline__ void pf_ld128fc(const float* __restrict__ g,
                                           size_t row0, int stride, int k0,
                                           uint2 r[8], int tid)
{
#pragma unroll
    for (int i = 0; i < 8; i++) {
        int idx = tid + i * 256;        // 0..2047
        int rr = idx >> 4, cc = idx & 15;
        float4 f = *reinterpret_cast<const float4*>(g + (row0 + rr) * (size_t)stride + k0 + cc * 4);
        r[i] = make_uint2(pack_f16(f.x, f.y), pack_f16(f.z, f.w));
    }
}
__device__ __forceinline__ void pf_st128c(const uint2 r[8], char* s, int tid)
{
#pragma unroll
    for (int i = 0; i < 8; i++) {
        int idx = tid + i * 256;
        int rr = idx >> 4, cc = idx & 15;
        *reinterpret_cast<uint2*>(s + SWZ((uint32_t)(rr * 128 + cc * 8))) = r[i];
    }
}
// ---- GEMM register prefetch (256 threads), fp16 source (16 regs) ----
__device__ __forceinline__ void pf_ld128h(const __half* __restrict__ g,
                                          size_t row0, int stride, int k0, uint4 r[4], int tid)
{
#pragma unroll
    for (int i = 0; i < 4; i++) {
        int idx = tid + i * 256;
        int rr = idx >> 3, cc = idx & 7;
        r[i] = *reinterpret_cast<const uint4*>(g + (row0 + rr) * (size_t)stride + k0 + cc * 8);
    }
}
__device__ __forceinline__ void pf_st128h(const uint4 r[4], char* s, int tid)
{
#pragma unroll
    for (int i = 0; i < 4; i++) {
        int idx = tid + i * 256;
        int rr = idx >> 3, cc = idx & 7;
        *reinterpret_cast<uint4*>(s + SWZ((uint32_t)(rr * 128 + cc * 16))) = r[i];
    }
}

// ---------------- fused QKV projection, 128x128 tiles, double-buffered, 1 sync/chunk ----------------
// smem: A0@0, B0@16K, A1@32K, B1@48K  (64KB/CTA, 2 CTAs/SM)
#define G_SMEM 65536

__global__ void __launch_bounds__(256, 2) gemm_qkv(
    const float* __restrict__ q, const float* __restrict__ k, const float* __restrict__ v,
    const float* __restrict__ Wq, const float* __restrict__ Wk, const float* __restrict__ Wv,
    const float* __restrict__ bq, const float* __restrict__ bk, const float* __restrict__ bv,
    __half* __restrict__ qp, __half* __restrict__ kp, __half* __restrict__ vtp)
{
    extern __shared__ char sm[];
    const int z = blockIdx.z;
    const float* X    = (z == 0) ? q  : (z == 1) ? k  : v;
    const float* W    = (z == 0) ? Wq : (z == 1) ? Wk : Wv;
    const float* bias = (z == 0) ? bq : (z == 1) ? bk : bv;
    __half* Oh        = (z == 0) ? qp : (z == 1) ? kp : vtp;
    const float oscale = (z == 0) ? QSCALE : 1.0f;

    const int tid = threadIdx.x, lane = tid & 31, wid = tid >> 5;
    const int wm = wid & 3, wn = wid >> 2;
    const int m0 = blockIdx.y * 128, n0 = blockIdx.x * 128;
    const uint32_t sb = smem_u32(sm);

    load_tile_f32<256>(X, (size_t)m0, EE, 0, sm + 0,     128, tid);
    load_tile_f32<256>(W, (size_t)n0, EE, 0, sm + 16384, 128, tid);
    __syncthreads();

    float c[2][8][4] = {};

    for (int chunk = 0; chunk < 8; chunk++) {
        const uint32_t cur = (chunk & 1) * 32768;
        uint2 pa[8], pb[8];
        if (chunk < 7) {
            const int k0 = (chunk + 1) * 64;
            pf_ld128fc(X, (size_t)m0, EE, k0, pa, tid);
            pf_ld128fc(W, (size_t)n0, EE, k0, pb, tid);
        }
#pragma unroll
        for (int kk = 0; kk < 4; kk++) {
            uint32_t af[2][4];
            ldsm4(af[0], addrA(sb + cur + 0, 32*wm,      kk*32, lane));
            ldsm4(af[1], addrA(sb + cur + 0, 32*wm + 16, kk*32, lane));
#pragma unroll
            for (int t = 0; t < 4; t++) {
                uint32_t bh[4];
                ldsm4(bh, addrB(sb + cur + 16384, 64*wn + 16*t, kk*32, lane));
#pragma unroll
                for (int mt = 0; mt < 2; mt++) {
                    mma_f16(c[mt][2*t],   af[mt], bh);
                    mma_f16(c[mt][2*t+1], af[mt], bh + 2);
                }
            }
        }
        if (chunk < 7) {
            const uint32_t oth = ((chunk + 1) & 1) * 32768;
            pf_st128c(pa, sm + oth + 0,     tid);
            pf_st128c(pb, sm + oth + 16384, tid);
        }
        __syncthreads();
    }

    const int g = lane >> 2, tig = lane & 3;
    if (z != 2) {
        // Q/K: [B,H,N,D], half2 stores
#pragma unroll
        for (int mt = 0; mt < 2; mt++) {
#pragma unroll
            for (int t = 0; t < 8; t++) {
                const int e = n0 + 64*wn + 8*t + 2*tig;
                const float bv0 = bias[e], bv1 = bias[e + 1];
#pragma unroll
                for (int hf = 0; hf < 2; hf++) {
                    const int m = m0 + 32*wm + 16*mt + g + 8*hf;
                    const float v0 = (c[mt][t][2*hf] + bv0) * oscale;
                    const float v1 = (c[mt][t][2*hf + 1] + bv1) * oscale;
                    const int bb = m >> 12, nn = m & (NN - 1);
                    const int hh = e >> 6, d = e & 63;
                    size_t idx = (((size_t)bb*HH + hh)*NN + nn)*DD + d;
                    *reinterpret_cast<uint32_t*>(Oh + idx) = pack_f16(v0, v1);
                }
            }
        }
    } else {
        // V: stage through smem (free after mainloop), emit coalesced [B,H,D,N] rows
        __half* st = reinterpret_cast<__half*>(sm);     // [128 e][136 pad] halves = 34.8KB
#pragma unroll
        for (int mt = 0; mt < 2; mt++) {
#pragma unroll
            for (int t = 0; t < 8; t++) {
                const int el = 64*wn + 8*t + 2*tig;
                const float bv0 = bias[n0 + el], bv1 = bias[n0 + el + 1];
#pragma unroll
                for (int hf = 0; hf < 2; hf++) {
                    const int ml = 32*wm + 16*mt + g + 8*hf;
                    st[el * 136 + ml]       = __float2half_rn(c[mt][t][2*hf] + bv0);
                    st[(el + 1) * 136 + ml] = __float2half_rn(c[mt][t][2*hf + 1] + bv1);
                }
            }
        }
        __syncthreads();
        const int bb = m0 >> 12;
        const int nbase = m0 & (NN - 1);
#pragma unroll
        for (int j = 0; j < 8; j++) {
            int i = tid + j * 256;          // 0..2047
            int r = i >> 4, cc = i & 15;    // e row, 8-half chunk
            uint4 val = *reinterpret_cast<const uint4*>(st + r * 136 + cc * 8);
            const int eg = n0 + r;
            const int hh = eg >> 6, d = eg & 63;
            *reinterpret_cast<uint4*>(Oh + (((size_t)bb*HH + hh)*DD + d)*NN + nbase + cc*8) = val;
        }
    }
}

// ---------------- output projection, 128x128 tiles, double-buffered, 1 sync/chunk ----------------
__global__ void __launch_bounds__(256, 2) gemm_o(
    const __half* __restrict__ A16, const float* __restrict__ W,
    const float* __restrict__ bias, float* __restrict__ Of)
{
    extern __shared__ char sm[];
    const int tid = threadIdx.x, lane = tid & 31, wid = tid >> 5;
    const int wm = wid & 3, wn = wid >> 2;
    const int m0 = blockIdx.y * 128, n0 = blockIdx.x * 128;
    const uint32_t sb = smem_u32(sm);

    load_tile<256>(A16, (size_t)m0, EE, 0, sm + 0,     128, tid);
    load_tile_f32<256>(W, (size_t)n0, EE, 0, sm + 16384, 128, tid);
    __syncthreads();

    float c[2][8][4] = {};

    for (int chunk = 0; chunk < 8; chunk++) {
        const uint32_t cur = (chunk & 1) * 32768;
        uint4 pa[4]; uint2 pb[8];
        if (chunk < 7) {
            const int k0 = (chunk + 1) * 64;
            pf_ld128h(A16, (size_t)m0, EE, k0, pa, tid);
            pf_ld128fc(W, (size_t)n0, EE, k0, pb, tid);
        }
#pragma unroll
        for (int kk = 0; kk < 4; kk++) {
            uint32_t af[2][4];
            ldsm4(af[0], addrA(sb + cur + 0, 32*wm,      kk*32, lane));
            ldsm4(af[1], addrA(sb + cur + 0, 32*wm + 16, kk*32, lane));
#pragma unroll
            for (int t = 0; t < 4; t++) {
                uint32_t bh[4];
                ldsm4(bh, addrB(sb + cur + 16384, 64*wn + 16*t, kk*32, lane));
#pragma unroll
                for (int mt = 0; mt < 2; mt++) {
                    mma_f16(c[mt][2*t],   af[mt], bh);
                    mma_f16(c[mt][2*t+1], af[mt], bh + 2);
                }
            }
        }
        if (chunk < 7) {
            const uint32_t oth = ((chunk + 1) & 1) * 32768;
            pf_st128h(pa, sm + oth + 0,     tid);
            pf_st128c(pb, sm + oth + 16384, tid);
        }
        __syncthreads();
    }

    const int g = lane >> 2, tig = lane & 3;
#pragma unroll
    for (int mt = 0; mt < 2; mt++) {
#pragma unroll
        for (int t = 0; t < 8; t++) {
            const int e = n0 + 64*wn + 8*t + 2*tig;
            const float bv0 = bias[e], bv1 = bias[e + 1];
#pragma unroll
            for (int hf = 0; hf < 2; hf++) {
                const int m = m0 + 32*wm + 16*mt + g + 8*hf;
                *reinterpret_cast<float2*>(Of + (size_t)m * EE + e) =
                    make_float2(c[mt][t][2*hf] + bv0, c[mt][t][2*hf + 1] + bv1);
            }
        }
    }
}

// ---------------- flash attention: round-14 structure + fp16-accum S (zero packs) ----------------
// CTA = 128 q-rows of one (b,h); 4 warps x 32 q-rows; 64-key tiles; 2 CTAs/SM; 1 sync/tile.
#define A_QH 0
#define A_KV0 16384        // stage s at A_KV0 + s*16384: K (8KB) then V (8KB)
#define A_SMEM 49152

__global__ void __launch_bounds__(128, 2) attn_mma(
    const __half* __restrict__ qp, const __half* __restrict__ kp,
    const __half* __restrict__ vt, __half* __restrict__ att)
{
    extern __shared__ char sm[];
    const int tid = threadIdx.x, lane = tid & 31, wid = tid >> 5;
    const int b = blockIdx.z, h = blockIdx.y, i0 = blockIdx.x * 128;
    const int bh = b * HH + h;
    const uint32_t sb = smem_u32(sm);

    load_tile<128>(qp, (size_t)bh * NN + i0, DD, 0, sm + A_QH, 128, tid);
    load_tile<128>(kp, (size_t)bh * NN, DD, 0, sm + A_KV0, 64, tid);
    load_tile<128>(vt, (size_t)bh * DD, NN, 0, sm + A_KV0 + 8192, 64, tid);
    __syncthreads();

    // Q fragments hoisted: constant across all key tiles
    uint32_t qf[4][2][4];
#pragma unroll
    for (int kk = 0; kk < 4; kk++) {
        ldsm4(qf[kk][0], addrA(sb + A_QH, 32*wid,      kk*32, lane));
        ldsm4(qf[kk][1], addrA(sb + A_QH, 32*wid + 16, kk*32, lane));
    }

    float o[2][8][4] = {};
    float lsum[2][2] = {};

    for (int t = 0; t < 64; t++) {
        const uint32_t bK = sb + A_KV0 + (t & 1) * 16384;
        const uint32_t bV = bK + 8192;
        char* nxt = sm + A_KV0 + ((t + 1) & 1) * 16384;

        uint4 kreg[4], vreg[4];
        if (t < 63) {
            pf_ld64s(kp, (size_t)bh * NN + (t + 1) * 64, DD, 0, kreg, tid);
            pf_ld64s(vt, (size_t)bh * DD, NN, (t + 1) * 64, vreg, tid);
        }

        // fp16 S accumulators: hsc[mt][nt][2] — D layout == PV A-fragment
        uint32_t hsc[2][8][2] = {};

        // exp + PV for key-slice j (16 keys): ex2 directly on fp16 accumulators
        auto exp_pv = [&](int j) {
            uint32_t ah[2][4];
#pragma unroll
            for (int mt = 0; mt < 2; mt++) {
                ah[mt][0] = h2ex2(hsc[mt][2*j][0]);      // row g,   keys 2tig..
                ah[mt][1] = h2ex2(hsc[mt][2*j][1]);      // row g+8, keys 2tig..
                ah[mt][2] = h2ex2(hsc[mt][2*j+1][0]);    // row g,   keys 8+2tig..
                ah[mt][3] = h2ex2(hsc[mt][2*j+1][1]);    // row g+8, keys 8+2tig..
                float2 f01 = h2f2(hadd2(ah[mt][0], ah[mt][2]));   // row g
                float2 f23 = h2f2(hadd2(ah[mt][1], ah[mt][3]));   // row g+8
                lsum[mt][0] += f01.x + f01.y;
                lsum[mt][1] += f23.x + f23.y;
            }
#pragma unroll
            for (int tv = 0; tv < 4; tv++) {
                uint32_t vh[4];
                ldsm4(vh, addrB(bV, 16*tv, j*32, lane));
#pragma unroll
                for (int mt = 0; mt < 2; mt++) {
                    mma_f16(o[mt][2*tv],   ah[mt], vh);
                    mma_f16(o[mt][2*tv+1], ah[mt], vh + 2);
                }
            }
        };

#pragma unroll
        for (int tt = 0; tt < 4; tt++) {
#pragma unroll
            for (int kk = 0; kk < 4; kk++) {
                uint32_t bhf[4];
                ldsm4(bhf, addrB(bK, 16*tt, kk*32, lane));
#pragma unroll
                for (int mt = 0; mt < 2; mt++) {
                    mma_f16h(hsc[mt][2*tt],   qf[kk][mt], bhf);
                    mma_f16h(hsc[mt][2*tt+1], qf[kk][mt], bhf + 2);
                }
            }
            if (tt > 0) exp_pv(tt - 1);
        }
        exp_pv(3);

        if (t < 63) {
            pf_st64s(kreg, nxt, tid);
            pf_st64s(vreg, nxt + 8192, tid);
        }
        __syncthreads();
    }

    // ---- reduce row sums across the 4 tig lanes, normalize, write fp16 ----
#pragma unroll
    for (int mt = 0; mt < 2; mt++)
#pragma unroll
        for (int hf = 0; hf < 2; hf++) {
            float s = lsum[mt][hf];
            s += __shfl_xor_sync(0xffffffffu, s, 1);
            s += __shfl_xor_sync(0xffffffffu, s, 2);
            lsum[mt][hf] = 1.0f / s;
        }

    const int g = lane >> 2, tig = lane & 3;
#pragma unroll
    for (int mt = 0; mt < 2; mt++) {
#pragma unroll
        for (int nt = 0; nt < 8; nt++) {
            const int d = 8*nt + 2*tig;
#pragma unroll
            for (int hf = 0; hf < 2; hf++) {
                const float inv = lsum[mt][hf];
                const int row = i0 + 32*wid + 16*mt + g + 8*hf;
                const size_t idx = ((size_t)b * NN + row) * EE + h * DD + d;
                *reinterpret_cast<uint32_t*>(att + idx) =
                    pack_f16(o[mt][nt][2*hf] * inv, o[mt][nt][2*hf + 1] * inv);
            }
        }
    }
}

// ---------------- host ----------------
extern "C" void kernel_launch(void* const* d_in, const int* in_sizes, int n_in,
                              void* d_out, int out_size)
{
    const float* q  = (const float*)d_in[0];
    const float* k  = (const float*)d_in[1];
    const float* v  = (const float*)d_in[2];
    const float* Wq = (const float*)d_in[3];
    const float* bq = (const float*)d_in[4];
    const float* Wk = (const float*)d_in[5];
    const float* bk = (const float*)d_in[6];
    const float* Wv = (const float*)d_in[7];
    const float* bv = (const float*)d_in[8];
    const float* Wo = (const float*)d_in[9];
    const float* bo = (const float*)d_in[10];
    float* out = (float*)d_out;

    __half* s;
    cudaGetSymbolAddress((void**)&s, g_scratch);
    __half *qp  = s,
           *kp  = s + (size_t)E1,
           *vtp = s + 2*(size_t)E1,
           *att = s + 3*(size_t)E1;

    cudaFuncSetAttribute(gemm_qkv, cudaFuncAttributeMaxDynamicSharedMemorySize, G_SMEM);
    cudaFuncSetAttribute(gemm_o,   cudaFuncAttributeMaxDynamicSharedMemorySize, G_SMEM);
    cudaFuncSetAttribute(attn_mma, cudaFuncAttributeMaxDynamicSharedMemorySize, A_SMEM);

    gemm_qkv<<<dim3(EE/128, MMR/128, 3), 256, G_SMEM>>>(
        q, k, v, Wq, Wk, Wv, bq, bk, bv, qp, kp, vtp);

    attn_mma<<<dim3(NN/128, HH, BB), 128, A_SMEM>>>(qp, kp, vtp, att);

    gemm_o<<<dim3(EE/128, MMR/128), 256, G_SMEM>>>(att, Wo, bo, out);
}

// round 17
// speedup vs baseline: 1.1254x; 1.0916x over previous
#include <cuda_runtime.h>
#include <cuda_fp16.h>
#include <stdint.h>

// ---------------- problem sizes ----------------
#define BB 2
#define NN 4096
#define EE 512
#define HH 8
#define DD 64
#define MMR (BB*NN)            // 8192
#define E1  (MMR*EE)           // 4194304
#define WSZ (EE*EE)            // 262144

// Q prescale: log2(e)/8, folded into the Q projection epilogue
#define QSCALE 0.18033688011112042f

// ---------------- scratch ----------------
__device__ __align__(256) __half g_scratch[8u*E1 + 4u*WSZ];

#define SWZ(o) ((o) ^ (((o) >> 3) & 0x70))

__device__ __forceinline__ uint32_t smem_u32(const void* p) {
    uint32_t a;
    asm("{ .reg .u64 t; cvta.to.shared.u64 t, %1; cvt.u32.u64 %0, t; }" : "=r"(a) : "l"(p));
    return a;
}
// ---- cp.async (sm_80+ PTX, portable) ----
#define CPA16(dst, src) \
    asm volatile("cp.async.cg.shared.global [%0], [%1], 16;" :: "r"(dst), "l"(src))
#define CP_COMMIT() asm volatile("cp.async.commit_group;" ::: "memory")
#define CP_WAIT0()  asm volatile("cp.async.wait_group 0;" ::: "memory")

__device__ __forceinline__ void mma_f16(float c[4], const uint32_t a[4], const uint32_t b[2]) {
    asm volatile("mma.sync.aligned.m16n8k16.row.col.f32.f16.f16.f32 "
        "{%0,%1,%2,%3}, {%4,%5,%6,%7}, {%8,%9}, {%0,%1,%2,%3};"
        : "+f"(c[0]), "+f"(c[1]), "+f"(c[2]), "+f"(c[3])
        : "r"(a[0]), "r"(a[1]), "r"(a[2]), "r"(a[3]), "r"(b[0]), "r"(b[1]));
}
// fp16-accumulator variant: D = {d0,d1} packed f16x2; layout == PV A-fragment
__device__ __forceinline__ void mma_f16h(uint32_t d[2], const uint32_t a[4], const uint32_t b[2]) {
    asm volatile("mma.sync.aligned.m16n8k16.row.col.f16.f16.f16.f16 "
        "{%0,%1}, {%2,%3,%4,%5}, {%6,%7}, {%0,%1};"
        : "+r"(d[0]), "+r"(d[1])
        : "r"(a[0]), "r"(a[1]), "r"(a[2]), "r"(a[3]), "r"(b[0]), "r"(b[1]));
}
__device__ __forceinline__ void ldsm4(uint32_t r[4], uint32_t addr) {
    asm volatile("ldmatrix.sync.aligned.m8n8.x4.shared.b16 {%0,%1,%2,%3}, [%4];"
        : "=r"(r[0]), "=r"(r[1]), "=r"(r[2]), "=r"(r[3]) : "r"(addr));
}
__device__ __forceinline__ uint32_t h2ex2(uint32_t x) {
    uint32_t r;
    asm("ex2.approx.f16x2 %0, %1;" : "=r"(r) : "r"(x));
    return r;
}
__device__ __forceinline__ uint32_t hadd2(uint32_t a, uint32_t b) {
    uint32_t r;
    asm("add.f16x2 %0, %1, %2;" : "=r"(r) : "r"(a), "r"(b));
    return r;
}
__device__ __forceinline__ float2 h2f2(uint32_t p) {
    __half2 h = *reinterpret_cast<__half2*>(&p);
    return __half22float2(h);
}
// A-operand x4: 16x16 tile at (rowbase, colByte); rows of 128B, SW128 swizzled
__device__ __forceinline__ uint32_t addrA(uint32_t base, int rowbase, int colByte, int lane) {
    int row = rowbase + (lane & 7) + (lane & 8);
    int col = colByte + ((lane >> 4) << 4);
    uint32_t off = (uint32_t)(row * 128 + col);
    return base + SWZ(off);
}
// B-operand x4: two n-tiles (16 rows) x 16 k-bytes
__device__ __forceinline__ uint32_t addrB(uint32_t base, int nbase, int kByte, int lane) {
    int row = nbase + (lane & 7) + (((lane >> 4) & 1) << 3);
    int col = kByte + (((lane >> 3) & 1) << 4);
    uint32_t off = (uint32_t)(row * 128 + col);
    return base + SWZ(off);
}
__device__ __forceinline__ uint32_t pack_f16(float lo, float hi) {
    uint32_t r;
    asm("cvt.rn.f16x2.f32 %0, %1, %2;" : "=r"(r) : "f"(hi), "f"(lo));
    return r;
}

// ---------------- fp32 -> fp16, float4 vectorized (proven in rounds 5-8) ----------------
__global__ void conv_f16_4(const float4* __restrict__ in, uint2* __restrict__ o16, int n4)
{
    int i = blockIdx.x * 256 + threadIdx.x;
    if (i < n4) {
        float4 f = in[i];
        o16[i] = make_uint2(pack_f16(f.x, f.y), pack_f16(f.z, f.w));
    }
}

// ---------------- tile loaders: nrows x 64 cols, SW128 rows of 128B ----------------
template<int NT>
__device__ __forceinline__ void load_tile(const __half* __restrict__ g,
                                          size_t row0, int stride, int k0,
                                          char* sdst, int nrows, int tid)
{
    const int total = nrows * 16;
    for (int i = tid; i < total; i += NT) {
        int r = i >> 4, c = i & 15;
        uint2 v = *reinterpret_cast<const uint2*>(g + (row0 + r) * (size_t)stride + k0 + c * 4);
        *reinterpret_cast<uint2*>(sdst + SWZ((uint32_t)(r * 128 + c * 8))) = v;
    }
}
// cp.async fp16 tile loader: nrows x 64 cols -> SW128 smem, 16B chunks
template<int NT>
__device__ __forceinline__ void cp_tile(const __half* __restrict__ g,
                                        size_t row0, int stride, int k0,
                                        uint32_t sdst, int nrows, int tid)
{
    const int total = nrows * 8;
    for (int i = tid; i < total; i += NT) {
        int r = i >> 3, c = i & 7;
        CPA16(sdst + SWZ((uint32_t)(r * 128 + c * 16)),
              g + (row0 + r) * (size_t)stride + k0 + c * 8);
    }
}

// ---- register prefetch, fp16: 64 rows x 64 cols, 128 threads (attention) ----
__device__ __forceinline__ void pf_ld64s(const __half* __restrict__ g,
                                         size_t row0, int stride, int k0,
                                         uint4 r[4], int tid)
{
#pragma unroll
    for (int i = 0; i < 4; i++) {
        int idx = tid + i * 128;
        int rr = idx >> 3, cc = idx & 7;
        r[i] = *reinterpret_cast<const uint4*>(g + (row0 + rr) * (size_t)stride + k0 + cc * 8);
    }
}
__device__ __forceinline__ void pf_st64s(const uint4 r[4], char* s, int tid)
{
#pragma unroll
    for (int i = 0; i < 4; i++) {
        int idx = tid + i * 128;
        int rr = idx >> 3, cc = idx & 7;
        *reinterpret_cast<uint4*>(s + SWZ((uint32_t)(rr * 128 + cc * 16))) = r[i];
    }
}

// ---------------- fused QKV projection: fp16 cp.async double-buffer, 1 sync/chunk ----------------
// smem: A0@0, B0@16K, A1@32K, B1@48K  (64KB/CTA, 2 CTAs/SM)
#define G_SMEM 65536

__global__ void __launch_bounds__(256, 2) gemm_qkv(
    const __half* __restrict__ xq, const __half* __restrict__ xk, const __half* __restrict__ xv,
    const __half* __restrict__ wq, const __half* __restrict__ wk, const __half* __restrict__ wv,
    const float* __restrict__ bq, const float* __restrict__ bk, const float* __restrict__ bv,
    __half* __restrict__ qp, __half* __restrict__ kp, __half* __restrict__ vtp)
{
    extern __shared__ char sm[];
    const int z = blockIdx.z;
    const __half* X   = (z == 0) ? xq : (z == 1) ? xk : xv;
    const __half* W   = (z == 0) ? wq : (z == 1) ? wk : wv;
    const float* bias = (z == 0) ? bq : (z == 1) ? bk : bv;
    __half* Oh        = (z == 0) ? qp : (z == 1) ? kp : vtp;
    const float oscale = (z == 0) ? QSCALE : 1.0f;

    const int tid = threadIdx.x, lane = tid & 31, wid = tid >> 5;
    const int wm = wid & 3, wn = wid >> 2;
    const int m0 = blockIdx.y * 128, n0 = blockIdx.x * 128;
    const uint32_t sb = smem_u32(sm);

    // chunk 0 into buffer 0
    cp_tile<256>(X, (size_t)m0, EE, 0, sb + 0,     128, tid);
    cp_tile<256>(W, (size_t)n0, EE, 0, sb + 16384, 128, tid);
    CP_COMMIT(); CP_WAIT0();
    __syncthreads();

    float c[2][8][4] = {};

    for (int chunk = 0; chunk < 8; chunk++) {
        const uint32_t cur = (chunk & 1) * 32768;
        if (chunk < 7) {
            const uint32_t oth = ((chunk + 1) & 1) * 32768;
            const int k0 = (chunk + 1) * 64;
            cp_tile<256>(X, (size_t)m0, EE, k0, sb + oth + 0,     128, tid);
            cp_tile<256>(W, (size_t)n0, EE, k0, sb + oth + 16384, 128, tid);
            CP_COMMIT();
        }
#pragma unroll
        for (int kk = 0; kk < 4; kk++) {
            uint32_t af[2][4];
            ldsm4(af[0], addrA(sb + cur + 0, 32*wm,      kk*32, lane));
            ldsm4(af[1], addrA(sb + cur + 0, 32*wm + 16, kk*32, lane));
#pragma unroll
            for (int t = 0; t < 4; t++) {
                uint32_t bh[4];
                ldsm4(bh, addrB(sb + cur + 16384, 64*wn + 16*t, kk*32, lane));
#pragma unroll
                for (int mt = 0; mt < 2; mt++) {
                    mma_f16(c[mt][2*t],   af[mt], bh);
                    mma_f16(c[mt][2*t+1], af[mt], bh + 2);
                }
            }
        }
        if (chunk < 7) CP_WAIT0();
        __syncthreads();
    }

    const int g = lane >> 2, tig = lane & 3;
    if (z != 2) {
        // Q/K: [B,H,N,D], half2 stores
#pragma unroll
        for (int mt = 0; mt < 2; mt++) {
#pragma unroll
            for (int t = 0; t < 8; t++) {
                const int e = n0 + 64*wn + 8*t + 2*tig;
                const float bv0 = bias[e], bv1 = bias[e + 1];
#pragma unroll
                for (int hf = 0; hf < 2; hf++) {
                    const int m = m0 + 32*wm + 16*mt + g + 8*hf;
                    const float v0 = (c[mt][t][2*hf] + bv0) * oscale;
                    const float v1 = (c[mt][t][2*hf + 1] + bv1) * oscale;
                    const int bb = m >> 12, nn = m & (NN - 1);
                    const int hh = e >> 6, d = e & 63;
                    size_t idx = (((size_t)bb*HH + hh)*NN + nn)*DD + d;
                    *reinterpret_cast<uint32_t*>(Oh + idx) = pack_f16(v0, v1);
                }
            }
        }
    } else {
        // V: stage through smem (free after mainloop), emit coalesced [B,H,D,N] rows
        __half* st = reinterpret_cast<__half*>(sm);     // [128 e][136 pad] halves = 34.8KB
#pragma unroll
        for (int mt = 0; mt < 2; mt++) {
#pragma unroll
            for (int t = 0; t < 8; t++) {
                const int el = 64*wn + 8*t + 2*tig;
                const float bv0 = bias[n0 + el], bv1 = bias[n0 + el + 1];
#pragma unroll
                for (int hf = 0; hf < 2; hf++) {
                    const int ml = 32*wm + 16*mt + g + 8*hf;
                    st[el * 136 + ml]       = __float2half_rn(c[mt][t][2*hf] + bv0);
                    st[(el + 1) * 136 + ml] = __float2half_rn(c[mt][t][2*hf + 1] + bv1);
                }
            }
        }
        __syncthreads();
        const int bb = m0 >> 12;
        const int nbase = m0 & (NN - 1);
#pragma unroll
        for (int j = 0; j < 8; j++) {
            int i = tid + j * 256;          // 0..2047
            int r = i >> 4, cc = i & 15;    // e row, 8-half chunk
            uint4 val = *reinterpret_cast<const uint4*>(st + r * 136 + cc * 8);
            const int eg = n0 + r;
            const int hh = eg >> 6, d = eg & 63;
            *reinterpret_cast<uint4*>(Oh + (((size_t)bb*HH + hh)*DD + d)*NN + nbase + cc*8) = val;
        }
    }
}

// ---------------- output projection: fp16 cp.async double-buffer, 1 sync/chunk ----------------
__global__ void __launch_bounds__(256, 2) gemm_o(
    const __half* __restrict__ A16, const __half* __restrict__ W16,
    const float* __restrict__ bias, float* __restrict__ Of)
{
    extern __shared__ char sm[];
    const int tid = threadIdx.x, lane = tid & 31, wid = tid >> 5;
    const int wm = wid & 3, wn = wid >> 2;
    const int m0 = blockIdx.y * 128, n0 = blockIdx.x * 128;
    const uint32_t sb = smem_u32(sm);

    cp_tile<256>(A16, (size_t)m0, EE, 0, sb + 0,     128, tid);
    cp_tile<256>(W16, (size_t)n0, EE, 0, sb + 16384, 128, tid);
    CP_COMMIT(); CP_WAIT0();
    __syncthreads();

    float c[2][8][4] = {};

    for (int chunk = 0; chunk < 8; chunk++) {
        const uint32_t cur = (chunk & 1) * 32768;
        if (chunk < 7) {
            const uint32_t oth = ((chunk + 1) & 1) * 32768;
            const int k0 = (chunk + 1) * 64;
            cp_tile<256>(A16, (size_t)m0, EE, k0, sb + oth + 0,     128, tid);
            cp_tile<256>(W16, (size_t)n0, EE, k0, sb + oth + 16384, 128, tid);
            CP_COMMIT();
        }
#pragma unroll
        for (int kk = 0; kk < 4; kk++) {
            uint32_t af[2][4];
            ldsm4(af[0], addrA(sb + cur + 0, 32*wm,      kk*32, lane));
            ldsm4(af[1], addrA(sb + cur + 0, 32*wm + 16, kk*32, lane));
#pragma unroll
            for (int t = 0; t < 4; t++) {
                uint32_t bh[4];
                ldsm4(bh, addrB(sb + cur + 16384, 64*wn + 16*t, kk*32, lane));
#pragma unroll
                for (int mt = 0; mt < 2; mt++) {
                    mma_f16(c[mt][2*t],   af[mt], bh);
                    mma_f16(c[mt][2*t+1], af[mt], bh + 2);
                }
            }
        }
        if (chunk < 7) CP_WAIT0();
        __syncthreads();
    }

    const int g = lane >> 2, tig = lane & 3;
#pragma unroll
    for (int mt = 0; mt < 2; mt++) {
#pragma unroll
        for (int t = 0; t < 8; t++) {
            const int e = n0 + 64*wn + 8*t + 2*tig;
            const float bv0 = bias[e], bv1 = bias[e + 1];
#pragma unroll
            for (int hf = 0; hf < 2; hf++) {
                const int m = m0 + 32*wm + 16*mt + g + 8*hf;
                *reinterpret_cast<float2*>(Of + (size_t)m * EE + e) =
                    make_float2(c[mt][t][2*hf] + bv0, c[mt][t][2*hf + 1] + bv1);
            }
        }
    }
}

// ---------------- flash attention: round-16 exactly (fp16-S, 64-key tiles) ----------------
#define A_QH 0
#define A_KV0 16384        // stage s at A_KV0 + s*16384: K (8KB) then V (8KB)
#define A_SMEM 49152

__global__ void __launch_bounds__(128, 2) attn_mma(
    const __half* __restrict__ qp, const __half* __restrict__ kp,
    const __half* __restrict__ vt, __half* __restrict__ att)
{
    extern __shared__ char sm[];
    const int tid = threadIdx.x, lane = tid & 31, wid = tid >> 5;
    const int b = blockIdx.z, h = blockIdx.y, i0 = blockIdx.x * 128;
    const int bh = b * HH + h;
    const uint32_t sb = smem_u32(sm);

    load_tile<128>(qp, (size_t)bh * NN + i0, DD, 0, sm + A_QH, 128, tid);
    load_tile<128>(kp, (size_t)bh * NN, DD, 0, sm + A_KV0, 64, tid);
    load_tile<128>(vt, (size_t)bh * DD, NN, 0, sm + A_KV0 + 8192, 64, tid);
    __syncthreads();

    uint32_t qf[4][2][4];
#pragma unroll
    for (int kk = 0; kk < 4; kk++) {
        ldsm4(qf[kk][0], addrA(sb + A_QH, 32*wid,      kk*32, lane));
        ldsm4(qf[kk][1], addrA(sb + A_QH, 32*wid + 16, kk*32, lane));
    }

    float o[2][8][4] = {};
    float lsum[2][2] = {};

    for (int t = 0; t < 64; t++) {
        const uint32_t bK = sb + A_KV0 + (t & 1) * 16384;
        const uint32_t bV = bK + 8192;
        char* nxt = sm + A_KV0 + ((t + 1) & 1) * 16384;

        uint4 kreg[4], vreg[4];
        if (t < 63) {
            pf_ld64s(kp, (size_t)bh * NN + (t + 1) * 64, DD, 0, kreg, tid);
            pf_ld64s(vt, (size_t)bh * DD, NN, (t + 1) * 64, vreg, tid);
        }

        uint32_t hsc[2][8][2] = {};

        auto exp_pv = [&](int j) {
            uint32_t ah[2][4];
#pragma unroll
            for (int mt = 0; mt < 2; mt++) {
                ah[mt][0] = h2ex2(hsc[mt][2*j][0]);
                ah[mt][1] = h2ex2(hsc[mt][2*j][1]);
                ah[mt][2] = h2ex2(hsc[mt][2*j+1][0]);
                ah[mt][3] = h2ex2(hsc[mt][2*j+1][1]);
                float2 f01 = h2f2(hadd2(ah[mt][0], ah[mt][2]));
                float2 f23 = h2f2(hadd2(ah[mt][1], ah[mt][3]));
                lsum[mt][0] += f01.x + f01.y;
                lsum[mt][1] += f23.x + f23.y;
            }
#pragma unroll
            for (int tv = 0; tv < 4; tv++) {
                uint32_t vh[4];
                ldsm4(vh, addrB(bV, 16*tv, j*32, lane));
#pragma unroll
                for (int mt = 0; mt < 2; mt++) {
                    mma_f16(o[mt][2*tv],   ah[mt], vh);
                    mma_f16(o[mt][2*tv+1], ah[mt], vh + 2);
                }
            }
        };

#pragma unroll
        for (int tt = 0; tt < 4; tt++) {
#pragma unroll
            for (int kk = 0; kk < 4; kk++) {
                uint32_t bhf[4];
                ldsm4(bhf, addrB(bK, 16*tt, kk*32, lane));
#pragma unroll
                for (int mt = 0; mt < 2; mt++) {
                    mma_f16h(hsc[mt][2*tt],   qf[kk][mt], bhf);
                    mma_f16h(hsc[mt][2*tt+1], qf[kk][mt], bhf + 2);
                }
            }
            if (tt > 0) exp_pv(tt - 1);
        }
        exp_pv(3);

        if (t < 63) {
            pf_st64s(kreg, nxt, tid);
            pf_st64s(vreg, nxt + 8192, tid);
        }
        __syncthreads();
    }

#pragma unroll
    for (int mt = 0; mt < 2; mt++)
#pragma unroll
        for (int hf = 0; hf < 2; hf++) {
            float s = lsum[mt][hf];
            s += __shfl_xor_sync(0xffffffffu, s, 1);
            s += __shfl_xor_sync(0xffffffffu, s, 2);
            lsum[mt][hf] = 1.0f / s;
        }

    const int g = lane >> 2, tig = lane & 3;
#pragma unroll
    for (int mt = 0; mt < 2; mt++) {
#pragma unroll
        for (int nt = 0; nt < 8; nt++) {
            const int d = 8*nt + 2*tig;
#pragma unroll
            for (int hf = 0; hf < 2; hf++) {
                const float inv = lsum[mt][hf];
                const int row = i0 + 32*wid + 16*mt + g + 8*hf;
                const size_t idx = ((size_t)b * NN + row) * EE + h * DD + d;
                *reinterpret_cast<uint32_t*>(att + idx) =
                    pack_f16(o[mt][nt][2*hf] * inv, o[mt][nt][2*hf + 1] * inv);
            }
        }
    }
}

// ---------------- host ----------------
extern "C" void kernel_launch(void* const* d_in, const int* in_sizes, int n_in,
                              void* d_out, int out_size)
{
    const float* q  = (const float*)d_in[0];
    const float* k  = (const float*)d_in[1];
    const float* v  = (const float*)d_in[2];
    const float* Wq = (const float*)d_in[3];
    const float* bq = (const float*)d_in[4];
    const float* Wk = (const float*)d_in[5];
    const float* bk = (const float*)d_in[6];
    const float* Wv = (const float*)d_in[7];
    const float* bv = (const float*)d_in[8];
    const float* Wo = (const float*)d_in[9];
    const float* bo = (const float*)d_in[10];
    float* out = (float*)d_out;

    __half* s;
    cudaGetSymbolAddress((void**)&s, g_scratch);
    __half *xq = s, *xk = s + (size_t)E1, *xv = s + 2*(size_t)E1;
    __half *wq = s + 3*(size_t)E1,
           *wk = wq + WSZ, *wv = wq + 2*WSZ, *wo = wq + 3*WSZ;
    __half *qp  = s + 3*(size_t)E1 + 4*(size_t)WSZ,
           *kp  = qp + (size_t)E1,
           *vtp = qp + 2*(size_t)E1,
           *att = qp + 3*(size_t)E1;

    cudaFuncSetAttribute(gemm_qkv, cudaFuncAttributeMaxDynamicSharedMemorySize, G_SMEM);
    cudaFuncSetAttribute(gemm_o,   cudaFuncAttributeMaxDynamicSharedMemorySize, G_SMEM);
    cudaFuncSetAttribute(attn_mma, cudaFuncAttributeMaxDynamicSharedMemorySize, A_SMEM);

    // pre-convert all operands to fp16 (proven-cheap kernels)
    conv_f16_4<<<E1/4/256, 256>>>((const float4*)q,  (uint2*)xq, E1/4);
    conv_f16_4<<<E1/4/256, 256>>>((const float4*)k,  (uint2*)xk, E1/4);
    conv_f16_4<<<E1/4/256, 256>>>((const float4*)v,  (uint2*)xv, E1/4);
    conv_f16_4<<<WSZ/4/256, 256>>>((const float4*)Wq, (uint2*)wq, WSZ/4);
    conv_f16_4<<<WSZ/4/256, 256>>>((const float4*)Wk, (uint2*)wk, WSZ/4);
    conv_f16_4<<<WSZ/4/256, 256>>>((const float4*)Wv, (uint2*)wv, WSZ/4);
    conv_f16_4<<<WSZ/4/256, 256>>>((const float4*)Wo, (uint2*)wo, WSZ/4);

    gemm_qkv<<<dim3(EE/128, MMR/128, 3), 256, G_SMEM>>>(
        xq, xk, xv, wq, wk, wv, bq, bk, bv, qp, kp, vtp);

    attn_mma<<<dim3(NN/128, HH, BB), 128, A_SMEM>>>(qp, kp, vtp, att);

    gemm_o<<<dim3(EE/128, MMR/128), 256, G_SMEM>>>(att, wo, bo, out);
}